// round 6
// baseline (speedup 1.0000x reference)
#include <cuda_runtime.h>
#include <cuda_bf16.h>
#include <cuda_fp16.h>
#include <cfloat>
#include <climits>
#include <cstdint>

// Problem constants
#define B_ 32768
#define D_ 512
#define L_ 4
#define K_ 1024
#define NROW (B_ + L_ * K_)   // 36864: z rows + all codebook rows
#define NCOL (L_ * K_)        // 4096: all codebook entries

// Candidate margin (score units). Screened-score error sigma ~0.016
// (bf16 z-dot + fp16 dot storage + correction-table noise); 0.25 ~ 15 sigma.
#define MARGIN 0.25f

// ---------------- scratch (__device__ globals; no allocations allowed) -----------
__device__ float          g_residual[(size_t)B_ * D_];   // fp32 residual, 64 MB
__device__ __nv_bfloat16  g_ab[(size_t)NROW * D_];       // bf16 [z ; codebooks], 36 MB
__device__ __half         g_dots[(size_t)NROW * NCOL];   // fp16 raw dots, 288 MB
__device__ float          g_c2[L_ * K_];
__device__ int            g_idx[L_][B_];
__device__ float          g_rowss[L_ * B_];

__device__ __forceinline__ uint32_t smem_u32(const void* p) {
    uint32_t a;
    asm("{ .reg .u64 t; cvta.to.shared.u64 t, %1; cvt.u32.u64 %0, t; }" : "=r"(a) : "l"(p));
    return a;
}

// ---------------- prep kernels ---------------------------------------------------
__global__ void conv_z_kernel(const float* __restrict__ z) {
    size_t i = ((size_t)blockIdx.x * blockDim.x + threadIdx.x) * 8;
    float4 a = *reinterpret_cast<const float4*>(z + i);
    float4 b = *reinterpret_cast<const float4*>(z + i + 4);
    __nv_bfloat162 h[4] = { __floats2bfloat162_rn(a.x, a.y), __floats2bfloat162_rn(a.z, a.w),
                            __floats2bfloat162_rn(b.x, b.y), __floats2bfloat162_rn(b.z, b.w) };
    *reinterpret_cast<uint4*>(g_ab + i) = *reinterpret_cast<uint4*>(h);
}

__global__ void conv_cb_kernel(const float* __restrict__ cb) {
    size_t i = ((size_t)blockIdx.x * blockDim.x + threadIdx.x) * 8;
    float4 a = *reinterpret_cast<const float4*>(cb + i);
    float4 b = *reinterpret_cast<const float4*>(cb + i + 4);
    __nv_bfloat162 h[4] = { __floats2bfloat162_rn(a.x, a.y), __floats2bfloat162_rn(a.z, a.w),
                            __floats2bfloat162_rn(b.x, b.y), __floats2bfloat162_rn(b.z, b.w) };
    *reinterpret_cast<uint4*>(g_ab + (size_t)B_ * D_ + i) = *reinterpret_cast<uint4*>(h);
}

// ||c||^2: fp64 accumulate -> fp32. One warp per codeword.
__global__ void c2_kernel(const float* __restrict__ cb) {
    int g = blockIdx.x * blockDim.x + threadIdx.x;
    int w = g >> 5, lane = g & 31;
    if (w >= L_ * K_) return;
    const float* row = cb + (size_t)w * D_;
    double s = 0.0;
    #pragma unroll 4
    for (int d = lane; d < D_; d += 32) { double v = (double)row[d]; s = fma(v, v, s); }
    #pragma unroll
    for (int o = 16; o; o >>= 1) s += __shfl_xor_sync(0xffffffffu, s, o);
    if (!lane) g_c2[w] = (float)s;
}

// ---------------- merged bf16 MMA GEMM -------------------------------------------
// One launch: [36864 x 512] x [512 x 4096]^T -> fp16 dots (z-dots + cross tables).
// CTA: 64 rows x all 4096 cols, 256 threads (8 warps, warp tile 32x32), 2 CTA/SM.
#define SM_A     0
#define SM_B     65536
#define SM_BBUF  16384
#define SM_TOTAL (65536 + 2 * 16384)

__device__ __forceinline__ void ldsm_x4(uint32_t* r, uint32_t addr) {
    asm volatile("ldmatrix.sync.aligned.m8n8.x4.shared.b16 {%0,%1,%2,%3}, [%4];"
        : "=r"(r[0]), "=r"(r[1]), "=r"(r[2]), "=r"(r[3]) : "r"(addr));
}
__device__ __forceinline__ void mma16816(float* c, const uint32_t* a, uint32_t b0, uint32_t b1) {
    asm volatile("mma.sync.aligned.m16n8k16.row.col.f32.bf16.bf16.f32 "
        "{%0,%1,%2,%3}, {%4,%5,%6,%7}, {%8,%9}, {%0,%1,%2,%3};"
        : "+f"(c[0]), "+f"(c[1]), "+f"(c[2]), "+f"(c[3])
        : "r"(a[0]), "r"(a[1]), "r"(a[2]), "r"(a[3]), "r"(b0), "r"(b1));
}

__global__ __launch_bounds__(256, 2) void gemm_kernel() {
    extern __shared__ char smem[];
    const int tid = threadIdx.x, wid = tid >> 5, lane = tid & 31;
    const int m0 = blockIdx.x * 64;
    const __nv_bfloat16* Bsrc = g_ab + (size_t)B_ * D_;   // codebook rows
    const uint32_t sb = smem_u32(smem);

    // Stage A via cp.async: 64 rows x 512 bf16, XOR-swizzled 16B chunks.
    #pragma unroll
    for (int i = 0; i < 16; i++) {
        int q = tid + i * 256;
        int m = q >> 6, c = q & 63;
        uint32_t dst = sb + SM_A + m * 1024 + ((c ^ (m & 7)) * 16);
        const void* g = g_ab + (size_t)(m0 + m) * D_ + c * 8;
        asm volatile("cp.async.cg.shared.global [%0], [%1], 16;" :: "r"(dst), "l"(g));
    }
    asm volatile("cp.async.commit_group;");

    // B chunk ci in 0..255: nt = ci>>3 (128-col tile), kc = ci&7 (64-k slab).
    #define LOAD_B_CHUNK(ci, buf) do {                                               \
        int _nt = (ci) >> 3, _kc = (ci) & 7;                                         \
        const __nv_bfloat16* _src = Bsrc + (size_t)(_nt * 128) * D_ + _kc * 64;      \
        _Pragma("unroll")                                                            \
        for (int _i = 0; _i < 4; _i++) {                                             \
            int _q = tid + _i * 256;                                                 \
            int _n = _q >> 3, _c = _q & 7;                                           \
            uint32_t _dst = sb + SM_B + (buf) * SM_BBUF + _n * 128 +                 \
                            ((_c ^ (_n & 7)) * 16);                                  \
            const void* _g = _src + (size_t)_n * D_ + _c * 8;                        \
            asm volatile("cp.async.cg.shared.global [%0], [%1], 16;"                 \
                         :: "r"(_dst), "l"(_g));                                     \
        }                                                                            \
        asm volatile("cp.async.commit_group;");                                      \
    } while (0)

    const int wm = wid & 1, wn = wid >> 1;   // warp tile: rows wm*32..+31, cols wn*32..+31
    const int lr = lane & 7;
    const int lh = (lane >> 3) & 1;
    const int lk = lane >> 4;

    LOAD_B_CHUNK(0, 0);

    float acc[2][4][4];

    for (int ci = 0; ci < 256; ci++) {
        const int buf = ci & 1;
        if (ci + 1 < 256) {
            LOAD_B_CHUNK(ci + 1, buf ^ 1);
            asm volatile("cp.async.wait_group 1;");
        } else {
            asm volatile("cp.async.wait_group 0;");
        }
        __syncthreads();
        const int nt = ci >> 3, kc = ci & 7;

        if (kc == 0) {
            #pragma unroll
            for (int mt = 0; mt < 2; mt++)
                #pragma unroll
                for (int nti = 0; nti < 4; nti++)
                    #pragma unroll
                    for (int q = 0; q < 4; q++) acc[mt][nti][q] = 0.f;
        }

        #pragma unroll
        for (int ks = 0; ks < 4; ks++) {
            uint32_t a[2][4];
            #pragma unroll
            for (int mt = 0; mt < 2; mt++) {
                int m = wm * 32 + mt * 16 + lh * 8 + lr;
                int ch = kc * 8 + ks * 2 + lk;
                uint32_t addr = sb + SM_A + m * 1024 + ((ch ^ (m & 7)) * 16);
                ldsm_x4(a[mt], addr);
            }
            uint32_t b[2][4];
            #pragma unroll
            for (int p = 0; p < 2; p++) {
                int n = wn * 32 + p * 16 + lk * 8 + lr;
                int ch = ks * 2 + lh;
                uint32_t addr = sb + SM_B + buf * SM_BBUF + n * 128 + ((ch ^ (n & 7)) * 16);
                ldsm_x4(b[p], addr);
            }
            #pragma unroll
            for (int mt = 0; mt < 2; mt++)
                #pragma unroll
                for (int nti = 0; nti < 4; nti++)
                    mma16816(acc[mt][nti], a[mt],
                             b[nti >> 1][(nti & 1) * 2 + 0],
                             b[nti >> 1][(nti & 1) * 2 + 1]);
        }

        if (kc == 7) {   // epilogue: fp16 raw dots for this 128-col tile
            #pragma unroll
            for (int mt = 0; mt < 2; mt++) {
                int row = m0 + wm * 32 + mt * 16 + (lane >> 2);
                #pragma unroll
                for (int nti = 0; nti < 4; nti++) {
                    int col = nt * 128 + wn * 32 + nti * 8 + (lane & 3) * 2;
                    __half2 h0 = __floats2half2_rn(acc[mt][nti][0], acc[mt][nti][1]);
                    __half2 h1 = __floats2half2_rn(acc[mt][nti][2], acc[mt][nti][3]);
                    *reinterpret_cast<__half2*>(g_dots + (size_t)row * NCOL + col) = h0;
                    *reinterpret_cast<__half2*>(g_dots + (size_t)(row + 8) * NCOL + col) = h1;
                }
            }
        }
        __syncthreads();
    }
    #undef LOAD_B_CHUNK
}

// ---------------- fused gather + argmin + exact rescore + residual update --------
// One warp per row. Score s_k = c2_k - 2*(dotz[b,k] - sum_prev T[idx_prev, k]).
// n==1 candidate => provably correct winner; else fp64-exact rescore
// (reference fp32 rounding chain). Then residual update, level vec, per-row
// sumsq, and at level 3 also quantized = z - residual.
__global__ __launch_bounds__(256) void argmin_update_kernel(const float* __restrict__ z,
                                                            const float* __restrict__ cb,
                                                            float* __restrict__ lv_base,
                                                            float* __restrict__ outq,
                                                            int level) {
    __shared__ int cnt[8];
    __shared__ int cand[8][32];
    const int tid = threadIdx.x, wid = tid >> 5, lane = tid & 31;
    const int b = blockIdx.x * 8 + wid;
    const float* prevres = level ? g_residual : z;
    const float* rrow = prevres + (size_t)b * D_;
    const float* cbl = cb + (size_t)level * K_ * D_;
    const float* c2l = g_c2 + level * K_;

    const __half2* dz = reinterpret_cast<const __half2*>(
        g_dots + (size_t)b * NCOL + level * K_);
    const __half2* cr[3];
    for (int lp = 0; lp < level; lp++)
        cr[lp] = reinterpret_cast<const __half2*>(
            g_dots + (size_t)(B_ + lp * K_ + g_idx[lp][b]) * NCOL + level * K_);

    // Scores: k = j*64 + lane*2 + {0,1}
    float s[32];
    float best = FLT_MAX;
    #pragma unroll
    for (int j = 0; j < 16; j++) {
        float2 v = __half22float2(dz[j * 32 + lane]);
        for (int lp = 0; lp < level; lp++) {
            float2 t = __half22float2(cr[lp][j * 32 + lane]);
            v.x -= t.x; v.y -= t.y;
        }
        float2 cv = *reinterpret_cast<const float2*>(c2l + j * 64 + lane * 2);
        s[j * 2 + 0] = fmaf(-2.f, v.x, cv.x);
        s[j * 2 + 1] = fmaf(-2.f, v.y, cv.y);
        best = fminf(best, fminf(s[j * 2 + 0], s[j * 2 + 1]));
    }
    #pragma unroll
    for (int o = 16; o; o >>= 1) best = fminf(best, __shfl_xor_sync(0xffffffffu, best, o));

    if (lane == 0) cnt[wid] = 0;
    __syncwarp();
    const float thr = best + MARGIN;
    #pragma unroll
    for (int j = 0; j < 16; j++)
        #pragma unroll
        for (int q = 0; q < 2; q++)
            if (s[j * 2 + q] <= thr) {
                int p = atomicAdd(&cnt[wid], 1);
                if (p < 32) cand[wid][p] = j * 64 + lane * 2 + q;
            }
    __syncwarp();
    int n = cnt[wid];
    int idx;
    if (n == 1) {
        idx = cand[wid][0];
    } else {
        // exact: fp64 dot + the reference's fp32 rounding chain
        double rd[16]; double r2 = 0.0;
        #pragma unroll
        for (int j = 0; j < 16; j++) {
            double v = (double)rrow[j * 32 + lane];
            rd[j] = v; r2 = fma(v, v, r2);
        }
        #pragma unroll
        for (int o = 16; o; o >>= 1) r2 += __shfl_xor_sync(0xffffffffu, r2, o);
        float r2f = (float)r2;

        float bestS = FLT_MAX; int bi = INT_MAX;
        if (n <= 32) {
            for (int t = 0; t < n; t++) {
                int k = cand[wid][t];
                const float* crow = cbl + (size_t)k * D_;
                double dp0 = 0.0, dp1 = 0.0;
                #pragma unroll
                for (int j = 0; j < 16; j += 2) {
                    dp0 = fma(rd[j],     (double)crow[j * 32 + lane],       dp0);
                    dp1 = fma(rd[j + 1], (double)crow[(j + 1) * 32 + lane], dp1);
                }
                double dp = dp0 + dp1;
                #pragma unroll
                for (int o = 16; o; o >>= 1) dp += __shfl_xor_sync(0xffffffffu, dp, o);
                float S = __fadd_rn(__fsub_rn(r2f, __fmul_rn(2.0f, (float)dp)), __ldg(c2l + k));
                if (S < bestS || (S == bestS && k < bi)) { bestS = S; bi = k; }
            }
        } else {
            for (int k = 0; k < K_; k++) {      // overflow fallback (~never)
                const float* crow = cbl + (size_t)k * D_;
                double dp0 = 0.0, dp1 = 0.0;
                #pragma unroll
                for (int j = 0; j < 16; j += 2) {
                    dp0 = fma(rd[j],     (double)crow[j * 32 + lane],       dp0);
                    dp1 = fma(rd[j + 1], (double)crow[(j + 1) * 32 + lane], dp1);
                }
                double dp = dp0 + dp1;
                #pragma unroll
                for (int o = 16; o; o >>= 1) dp += __shfl_xor_sync(0xffffffffu, dp, o);
                float S = __fadd_rn(__fsub_rn(r2f, __fmul_rn(2.0f, (float)dp)), __ldg(c2l + k));
                if (S < bestS) { bestS = S; bi = k; }
            }
        }
        idx = bi;
    }
    if (lane == 0) g_idx[level][b] = idx;

    // ---- update phase ----
    const float4* c  = reinterpret_cast<const float4*>(cbl + (size_t)idx * D_);
    const float4* r  = reinterpret_cast<const float4*>(rrow);
    float4* ro = reinterpret_cast<float4*>(g_residual + (size_t)b * D_);
    float4* lo = reinterpret_cast<float4*>(lv_base + (size_t)level * B_ * D_ + (size_t)b * D_);
    const float4* zv = reinterpret_cast<const float4*>(z + (size_t)b * D_);
    float4* oq = reinterpret_cast<float4*>(outq + (size_t)b * D_);
    float ss = 0.f;
    #pragma unroll
    for (int d = lane; d < D_ / 4; d += 32) {
        float4 rv = r[d], cv = c[d];
        float4 nv = make_float4(rv.x - cv.x, rv.y - cv.y, rv.z - cv.z, rv.w - cv.w);
        ro[d] = nv;
        lo[d] = cv;
        if (level == 3) {
            float4 zq = zv[d];
            oq[d] = make_float4(zq.x - nv.x, zq.y - nv.y, zq.z - nv.z, zq.w - nv.w);
        }
        ss = fmaf(nv.x, nv.x, fmaf(nv.y, nv.y, fmaf(nv.z, nv.z, fmaf(nv.w, nv.w, ss))));
    }
    #pragma unroll
    for (int o = 16; o; o >>= 1) ss += __shfl_xor_sync(0xffffffffu, ss, o);
    if (!lane) g_rowss[level * B_ + b] = ss;
}

// ---------------- loss -----------------------------------------------------------
__global__ void loss_kernel(float* __restrict__ out) {
    __shared__ double sh[256];
    __shared__ float means[L_];
    int t = threadIdx.x;
    for (int l = 0; l < L_; l++) {
        double s = 0.0;
        for (int i = t; i < B_; i += 256) s += (double)g_rowss[l * B_ + i];
        sh[t] = s; __syncthreads();
        for (int o = 128; o; o >>= 1) { if (t < o) sh[t] += sh[t + o]; __syncthreads(); }
        if (t == 0) means[l] = (float)(sh[0] / ((double)B_ * (double)D_));
        __syncthreads();
    }
    if (t == 0) {
        float loss = 0.f;
        for (int l = 0; l < L_; l++) loss = __fadd_rn(loss, means[l]);
        out[0] = loss;
    }
}

// ---------------- launcher -------------------------------------------------------
extern "C" void kernel_launch(void* const* d_in, const int* in_sizes, int n_in,
                              void* d_out, int out_size) {
    const float* z  = (const float*)d_in[0];   // [B, D]
    const float* cb = (const float*)d_in[1];   // [L, K, D]
    float* out = (float*)d_out;
    float* outq  = out;
    float* outlv = out + (size_t)B_ * D_;
    float* outls = out + (size_t)B_ * D_ * (size_t)(1 + L_);

    static bool attr_set = false;
    if (!attr_set) {
        cudaFuncSetAttribute(gemm_kernel, cudaFuncAttributeMaxDynamicSharedMemorySize, SM_TOTAL);
        attr_set = true;
    }

    conv_z_kernel<<<(B_ * D_ / 8) / 256, 256>>>(z);
    conv_cb_kernel<<<(L_ * K_ * D_ / 8) / 256, 256>>>(cb);
    c2_kernel<<<(L_ * K_ * 32) / 256, 256>>>(cb);

    gemm_kernel<<<NROW / 64, 256, SM_TOTAL>>>();

    for (int l = 0; l < L_; l++)
        argmin_update_kernel<<<B_ / 8, 256>>>(z, cb, outlv, outq, l);

    loss_kernel<<<1, 256>>>(outls);
}

// round 7
// speedup vs baseline: 1.4337x; 1.4337x over previous
#include <cuda_runtime.h>
#include <cuda_bf16.h>
#include <cfloat>
#include <climits>
#include <cstdint>

// Problem constants
#define B_ 32768
#define D_ 512
#define L_ 4
#define K_ 1024

// Candidate margin (score units). Screened-score error now only bf16-GEMM
// noise (sigma ~0.014, no fp16 storage term); 0.15 ~ 10 sigma. n==1 final
// candidate => provably the reference argmin; otherwise exact fp64 rescore.
#define MARGIN 0.15f
#define MAXCAND 12

// ---------------- scratch (__device__ globals; no allocations allowed) -----------
__device__ float          g_residual[(size_t)B_ * D_];   // fp32 residual, 64 MB
__device__ __nv_bfloat16  g_rb[(size_t)B_ * D_];         // bf16 residual (GEMM A), 32 MB
__device__ __nv_bfloat16  g_cbh[(size_t)L_ * K_ * D_];   // bf16 codebooks, 4 MB
__device__ float          g_c2[L_ * K_];
__device__ int            g_ccnt[B_];
__device__ int            g_cand[B_][MAXCAND];
__device__ float          g_rowss[L_ * B_];

__device__ __forceinline__ uint32_t smem_u32(const void* p) {
    uint32_t a;
    asm("{ .reg .u64 t; cvta.to.shared.u64 t, %1; cvt.u32.u64 %0, t; }" : "=r"(a) : "l"(p));
    return a;
}
// order-preserving float <-> uint map (for atomicMin on scores, incl. negatives)
__device__ __forceinline__ unsigned fkey(float f) {
    unsigned u = __float_as_uint(f);
    return (u & 0x80000000u) ? ~u : (u | 0x80000000u);
}
__device__ __forceinline__ float fdec(unsigned k) {
    unsigned u = (k & 0x80000000u) ? (k ^ 0x80000000u) : ~k;
    return __uint_as_float(u);
}

// ---------------- prep kernels ---------------------------------------------------
__global__ void conv_z_kernel(const float* __restrict__ z) {
    size_t i = ((size_t)blockIdx.x * blockDim.x + threadIdx.x) * 8;
    float4 a = *reinterpret_cast<const float4*>(z + i);
    float4 b = *reinterpret_cast<const float4*>(z + i + 4);
    __nv_bfloat162 h[4] = { __floats2bfloat162_rn(a.x, a.y), __floats2bfloat162_rn(a.z, a.w),
                            __floats2bfloat162_rn(b.x, b.y), __floats2bfloat162_rn(b.z, b.w) };
    *reinterpret_cast<uint4*>(g_rb + i) = *reinterpret_cast<uint4*>(h);
}

__global__ void conv_cb_kernel(const float* __restrict__ cb) {
    size_t i = ((size_t)blockIdx.x * blockDim.x + threadIdx.x) * 8;
    float4 a = *reinterpret_cast<const float4*>(cb + i);
    float4 b = *reinterpret_cast<const float4*>(cb + i + 4);
    __nv_bfloat162 h[4] = { __floats2bfloat162_rn(a.x, a.y), __floats2bfloat162_rn(a.z, a.w),
                            __floats2bfloat162_rn(b.x, b.y), __floats2bfloat162_rn(b.z, b.w) };
    *reinterpret_cast<uint4*>(g_cbh + i) = *reinterpret_cast<uint4*>(h);
}

// ||c||^2: fp64 accumulate -> fp32. One warp per codeword.
__global__ void c2_kernel(const float* __restrict__ cb) {
    int g = blockIdx.x * blockDim.x + threadIdx.x;
    int w = g >> 5, lane = g & 31;
    if (w >= L_ * K_) return;
    const float* row = cb + (size_t)w * D_;
    double s = 0.0;
    #pragma unroll 4
    for (int d = lane; d < D_; d += 32) { double v = (double)row[d]; s = fma(v, v, s); }
    #pragma unroll
    for (int o = 16; o; o >>= 1) s += __shfl_xor_sync(0xffffffffu, s, o);
    if (!lane) g_c2[w] = (float)s;
}

// ---------------- bf16 MMA GEMM + fused min/candidate epilogue -------------------
// Per CTA: 64 rows x all 1024 codes, K=512. 256 threads, warp tile 32x32,
// 2 CTA/SM. No score matrix in DRAM: per-row global min + candidate list only.
#define SM_A     0
#define SM_B     65536
#define SM_BBUF  16384
#define SM_TOTAL (65536 + 2 * 16384)

__device__ __forceinline__ void ldsm_x4(uint32_t* r, uint32_t addr) {
    asm volatile("ldmatrix.sync.aligned.m8n8.x4.shared.b16 {%0,%1,%2,%3}, [%4];"
        : "=r"(r[0]), "=r"(r[1]), "=r"(r[2]), "=r"(r[3]) : "r"(addr));
}
__device__ __forceinline__ void mma16816(float* c, const uint32_t* a, uint32_t b0, uint32_t b1) {
    asm volatile("mma.sync.aligned.m16n8k16.row.col.f32.bf16.bf16.f32 "
        "{%0,%1,%2,%3}, {%4,%5,%6,%7}, {%8,%9}, {%0,%1,%2,%3};"
        : "+f"(c[0]), "+f"(c[1]), "+f"(c[2]), "+f"(c[3])
        : "r"(a[0]), "r"(a[1]), "r"(a[2]), "r"(a[3]), "r"(b0), "r"(b1));
}

__global__ __launch_bounds__(256, 2) void gemm_kernel(int level) {
    extern __shared__ char smem[];
    __shared__ unsigned bestKey[64];
    __shared__ int   ccnt[64];
    __shared__ int   candI[64][MAXCAND];
    __shared__ float candS[64][MAXCAND];

    const int tid = threadIdx.x, wid = tid >> 5, lane = tid & 31;
    const int m0 = blockIdx.x * 64;
    const __nv_bfloat16* Bsrc = g_cbh + (size_t)level * K_ * D_;
    const float* c2l = g_c2 + level * K_;
    const uint32_t sb = smem_u32(smem);

    if (tid < 64) { bestKey[tid] = 0xFFFFFFFFu; ccnt[tid] = 0; }

    // Stage A via cp.async: 64 rows x 512 bf16, XOR-swizzled 16B chunks.
    #pragma unroll
    for (int i = 0; i < 16; i++) {
        int q = tid + i * 256;
        int m = q >> 6, c = q & 63;
        uint32_t dst = sb + SM_A + m * 1024 + ((c ^ (m & 7)) * 16);
        const void* g = g_rb + (size_t)(m0 + m) * D_ + c * 8;
        asm volatile("cp.async.cg.shared.global [%0], [%1], 16;" :: "r"(dst), "l"(g));
    }
    asm volatile("cp.async.commit_group;");

    // B chunk ci in 0..63: nt = ci>>3 (128-col tile), kc = ci&7 (64-k slab).
    #define LOAD_B_CHUNK(ci, buf) do {                                               \
        int _nt = (ci) >> 3, _kc = (ci) & 7;                                         \
        const __nv_bfloat16* _src = Bsrc + (size_t)(_nt * 128) * D_ + _kc * 64;      \
        _Pragma("unroll")                                                            \
        for (int _i = 0; _i < 4; _i++) {                                             \
            int _q = tid + _i * 256;                                                 \
            int _n = _q >> 3, _c = _q & 7;                                           \
            uint32_t _dst = sb + SM_B + (buf) * SM_BBUF + _n * 128 +                 \
                            ((_c ^ (_n & 7)) * 16);                                  \
            const void* _g = _src + (size_t)_n * D_ + _c * 8;                        \
            asm volatile("cp.async.cg.shared.global [%0], [%1], 16;"                 \
                         :: "r"(_dst), "l"(_g));                                     \
        }                                                                            \
        asm volatile("cp.async.commit_group;");                                      \
    } while (0)

    const int wm = wid & 1, wn = wid >> 1;   // warp tile: rows wm*32..+31, cols wn*32..+31
    const int lr = lane & 7;
    const int lh = (lane >> 3) & 1;
    const int lk = lane >> 4;

    LOAD_B_CHUNK(0, 0);

    float acc[2][4][4];

    for (int ci = 0; ci < 64; ci++) {
        const int buf = ci & 1;
        if (ci + 1 < 64) {
            LOAD_B_CHUNK(ci + 1, buf ^ 1);
            asm volatile("cp.async.wait_group 1;");
        } else {
            asm volatile("cp.async.wait_group 0;");
        }
        __syncthreads();
        const int nt = ci >> 3, kc = ci & 7;

        if (kc == 0) {
            #pragma unroll
            for (int mt = 0; mt < 2; mt++)
                #pragma unroll
                for (int nti = 0; nti < 4; nti++)
                    #pragma unroll
                    for (int q = 0; q < 4; q++) acc[mt][nti][q] = 0.f;
        }

        #pragma unroll
        for (int ks = 0; ks < 4; ks++) {
            uint32_t a[2][4];
            #pragma unroll
            for (int mt = 0; mt < 2; mt++) {
                int m = wm * 32 + mt * 16 + lh * 8 + lr;
                int ch = kc * 8 + ks * 2 + lk;
                uint32_t addr = sb + SM_A + m * 1024 + ((ch ^ (m & 7)) * 16);
                ldsm_x4(a[mt], addr);
            }
            uint32_t b[2][4];
            #pragma unroll
            for (int p = 0; p < 2; p++) {
                int n = wn * 32 + p * 16 + lk * 8 + lr;
                int ch = ks * 2 + lh;
                uint32_t addr = sb + SM_B + buf * SM_BBUF + n * 128 + ((ch ^ (n & 7)) * 16);
                ldsm_x4(b[p], addr);
            }
            #pragma unroll
            for (int mt = 0; mt < 2; mt++)
                #pragma unroll
                for (int nti = 0; nti < 4; nti++)
                    mma16816(acc[mt][nti], a[mt],
                             b[nti >> 1][(nti & 1) * 2 + 0],
                             b[nti >> 1][(nti & 1) * 2 + 1]);
        }

        if (kc == 7) {
            // ---- fused epilogue for this 128-col tile ----
            // Thread covers rows {wm*32+mt*16+(lane>>2), +8} x cols
            // {nt*128 + wn*32 + nti*8 + (lane&3)*2, +1}. Score = c2 - 2*dot.
            // pass 1: per-row running global min (ordered-uint atomicMin)
            #pragma unroll
            for (int mt = 0; mt < 2; mt++) {
                #pragma unroll
                for (int h = 0; h < 2; h++) {
                    int row = wm * 32 + mt * 16 + h * 8 + (lane >> 2);
                    float lmin = FLT_MAX;
                    #pragma unroll
                    for (int nti = 0; nti < 4; nti++) {
                        int col = nt * 128 + wn * 32 + nti * 8 + (lane & 3) * 2;
                        float2 cv = *reinterpret_cast<const float2*>(c2l + col);
                        float s0 = fmaf(-2.f, acc[mt][nti][h * 2 + 0], cv.x);
                        float s1 = fmaf(-2.f, acc[mt][nti][h * 2 + 1], cv.y);
                        lmin = fminf(lmin, fminf(s0, s1));
                    }
                    atomicMin(&bestKey[row], fkey(lmin));
                }
            }
            __syncthreads();
            // pass 2: collect candidates vs (running min + MARGIN)  [superset of final]
            #pragma unroll
            for (int mt = 0; mt < 2; mt++) {
                #pragma unroll
                for (int h = 0; h < 2; h++) {
                    int row = wm * 32 + mt * 16 + h * 8 + (lane >> 2);
                    float thr = fdec(bestKey[row]) + MARGIN;
                    #pragma unroll
                    for (int nti = 0; nti < 4; nti++) {
                        int col = nt * 128 + wn * 32 + nti * 8 + (lane & 3) * 2;
                        float2 cv = *reinterpret_cast<const float2*>(c2l + col);
                        float s0 = fmaf(-2.f, acc[mt][nti][h * 2 + 0], cv.x);
                        float s1 = fmaf(-2.f, acc[mt][nti][h * 2 + 1], cv.y);
                        if (s0 <= thr) {
                            int p = atomicAdd(&ccnt[row], 1);
                            if (p < MAXCAND) { candI[row][p] = col; candS[row][p] = s0; }
                        }
                        if (s1 <= thr) {
                            int p = atomicAdd(&ccnt[row], 1);
                            if (p < MAXCAND) { candI[row][p] = col + 1; candS[row][p] = s1; }
                        }
                    }
                }
            }
        }
        __syncthreads();
    }
    #undef LOAD_B_CHUNK

    // Final per-row filter & writeout (one thread per row).
    if (tid < 64) {
        int b = m0 + tid;
        int c = ccnt[tid];
        if (c > MAXCAND) {
            g_ccnt[b] = 999;                       // overflow: full exact rescan
        } else {
            float thr = fdec(bestKey[tid]) + MARGIN;
            int m = 0;
            for (int i = 0; i < c; i++)
                if (candS[tid][i] <= thr) g_cand[b][m++] = candI[tid][i];
            g_ccnt[b] = m;                          // m >= 1 always (min itself)
        }
    }
}

// ---------------- fused candidate-resolve + exact rescore + residual update ------
// One warp per row. ccnt==1 => provably correct winner; else fp64-exact rescore
// of candidates (reference fp32 rounding chain, lowest-index ties). Then residual
// update, level vec, bf16 mirror (levels 0-2), per-row sumsq, and at level 3 also
// quantized = z - residual.
__global__ __launch_bounds__(256) void argmin_update_kernel(const float* __restrict__ z,
                                                            const float* __restrict__ cb,
                                                            float* __restrict__ lv_base,
                                                            float* __restrict__ outq,
                                                            int level) {
    const int tid = threadIdx.x, wid = tid >> 5, lane = tid & 31;
    const int b = blockIdx.x * 8 + wid;
    const float* prevres = level ? g_residual : z;
    const float* rrow = prevres + (size_t)b * D_;
    const float* cbl = cb + (size_t)level * K_ * D_;
    const float* c2l = g_c2 + level * K_;

    int n = g_ccnt[b];
    int idx;
    if (n == 1) {
        idx = g_cand[b][0];
    } else {
        // exact: fp64 dot + the reference's fp32 rounding chain
        double rd[16]; double r2 = 0.0;
        #pragma unroll
        for (int j = 0; j < 16; j++) {
            double v = (double)rrow[j * 32 + lane];
            rd[j] = v; r2 = fma(v, v, r2);
        }
        #pragma unroll
        for (int o = 16; o; o >>= 1) r2 += __shfl_xor_sync(0xffffffffu, r2, o);
        float r2f = (float)r2;

        float bestS = FLT_MAX; int bi = INT_MAX;
        if (n <= MAXCAND) {
            for (int t = 0; t < n; t++) {
                int k = g_cand[b][t];
                const float* crow = cbl + (size_t)k * D_;
                double dp0 = 0.0, dp1 = 0.0;
                #pragma unroll
                for (int j = 0; j < 16; j += 2) {
                    dp0 = fma(rd[j],     (double)crow[j * 32 + lane],       dp0);
                    dp1 = fma(rd[j + 1], (double)crow[(j + 1) * 32 + lane], dp1);
                }
                double dp = dp0 + dp1;
                #pragma unroll
                for (int o = 16; o; o >>= 1) dp += __shfl_xor_sync(0xffffffffu, dp, o);
                float S = __fadd_rn(__fsub_rn(r2f, __fmul_rn(2.0f, (float)dp)), __ldg(c2l + k));
                if (S < bestS || (S == bestS && k < bi)) { bestS = S; bi = k; }
            }
        } else {
            for (int k = 0; k < K_; k++) {          // overflow fallback (~never)
                const float* crow = cbl + (size_t)k * D_;
                double dp0 = 0.0, dp1 = 0.0;
                #pragma unroll
                for (int j = 0; j < 16; j += 2) {
                    dp0 = fma(rd[j],     (double)crow[j * 32 + lane],       dp0);
                    dp1 = fma(rd[j + 1], (double)crow[(j + 1) * 32 + lane], dp1);
                }
                double dp = dp0 + dp1;
                #pragma unroll
                for (int o = 16; o; o >>= 1) dp += __shfl_xor_sync(0xffffffffu, dp, o);
                float S = __fadd_rn(__fsub_rn(r2f, __fmul_rn(2.0f, (float)dp)), __ldg(c2l + k));
                if (S < bestS) { bestS = S; bi = k; }
            }
        }
        idx = bi;
    }

    // ---- update phase ----
    const float4* c  = reinterpret_cast<const float4*>(cbl + (size_t)idx * D_);
    const float4* r  = reinterpret_cast<const float4*>(rrow);
    float4* ro = reinterpret_cast<float4*>(g_residual + (size_t)b * D_);
    float4* lo = reinterpret_cast<float4*>(lv_base + (size_t)level * B_ * D_ + (size_t)b * D_);
    const float4* zv = reinterpret_cast<const float4*>(z + (size_t)b * D_);
    float4* oq = reinterpret_cast<float4*>(outq + (size_t)b * D_);
    float ss = 0.f;
    #pragma unroll
    for (int d = lane; d < D_ / 4; d += 32) {
        float4 rv = r[d], cv = c[d];
        float4 nv = make_float4(rv.x - cv.x, rv.y - cv.y, rv.z - cv.z, rv.w - cv.w);
        ro[d] = nv;
        lo[d] = cv;
        if (level < 3) {
            __nv_bfloat162 h0 = __floats2bfloat162_rn(nv.x, nv.y);
            __nv_bfloat162 h1 = __floats2bfloat162_rn(nv.z, nv.w);
            uint2 pk = make_uint2(*reinterpret_cast<uint32_t*>(&h0),
                                  *reinterpret_cast<uint32_t*>(&h1));
            *reinterpret_cast<uint2*>(g_rb + (size_t)b * D_ + d * 4) = pk;
        } else {
            float4 zq = zv[d];
            oq[d] = make_float4(zq.x - nv.x, zq.y - nv.y, zq.z - nv.z, zq.w - nv.w);
        }
        ss = fmaf(nv.x, nv.x, fmaf(nv.y, nv.y, fmaf(nv.z, nv.z, fmaf(nv.w, nv.w, ss))));
    }
    #pragma unroll
    for (int o = 16; o; o >>= 1) ss += __shfl_xor_sync(0xffffffffu, ss, o);
    if (!lane) g_rowss[level * B_ + b] = ss;
}

// ---------------- loss -----------------------------------------------------------
__global__ void loss_kernel(float* __restrict__ out) {
    __shared__ double sh[256];
    __shared__ float means[L_];
    int t = threadIdx.x;
    for (int l = 0; l < L_; l++) {
        double s = 0.0;
        for (int i = t; i < B_; i += 256) s += (double)g_rowss[l * B_ + i];
        sh[t] = s; __syncthreads();
        for (int o = 128; o; o >>= 1) { if (t < o) sh[t] += sh[t + o]; __syncthreads(); }
        if (t == 0) means[l] = (float)(sh[0] / ((double)B_ * (double)D_));
        __syncthreads();
    }
    if (t == 0) {
        float loss = 0.f;
        for (int l = 0; l < L_; l++) loss = __fadd_rn(loss, means[l]);
        out[0] = loss;
    }
}

// ---------------- launcher -------------------------------------------------------
extern "C" void kernel_launch(void* const* d_in, const int* in_sizes, int n_in,
                              void* d_out, int out_size) {
    const float* z  = (const float*)d_in[0];   // [B, D]
    const float* cb = (const float*)d_in[1];   // [L, K, D]
    float* out = (float*)d_out;
    float* outq  = out;
    float* outlv = out + (size_t)B_ * D_;
    float* outls = out + (size_t)B_ * D_ * (size_t)(1 + L_);

    static bool attr_set = false;
    if (!attr_set) {
        cudaFuncSetAttribute(gemm_kernel, cudaFuncAttributeMaxDynamicSharedMemorySize, SM_TOTAL);
        attr_set = true;
    }

    conv_z_kernel<<<(B_ * D_ / 8) / 256, 256>>>(z);
    conv_cb_kernel<<<(L_ * K_ * D_ / 8) / 256, 256>>>(cb);
    c2_kernel<<<(L_ * K_ * 32) / 256, 256>>>(cb);

    for (int l = 0; l < L_; l++) {
        gemm_kernel<<<B_ / 64, 256, SM_TOTAL>>>(l);
        argmin_update_kernel<<<B_ / 8, 256>>>(z, cb, outlv, outq, l);
    }

    loss_kernel<<<1, 256>>>(outls);
}